// round 6
// baseline (speedup 1.0000x reference)
#include <cuda_runtime.h>
#include <cuda_fp16.h>
#include <cuda_bf16.h>
#include <mma.h>

using namespace nvcuda;

#define MAX_NODES 100000
#define MAX_EDGES 640000

// Scratch (device globals — allocation in kernel_launch is forbidden)
__device__ __half g_Yh[(size_t)MAX_NODES * 128];        // Y = X@W fp16 (25.6 MB)
__device__ int    g_hist[MAX_NODES + 256];              // counts; [N+1] = base counter
__device__ int    g_start[MAX_NODES + 1];
__device__ int    g_cursor[MAX_NODES];
__device__ int    g_src[MAX_EDGES];                     // sources grouped by dest

// Static-initializer stream/event creation (host-side).
struct SideStream {
    cudaStream_t s;
    cudaEvent_t fork, join;
    SideStream() {
        cudaStreamCreateWithFlags(&s, cudaStreamNonBlocking);
        cudaEventCreateWithFlags(&fork, cudaEventDisableTiming);
        cudaEventCreateWithFlags(&join, cudaEventDisableTiming);
    }
};
static SideStream g_ss;

// ---------------------------------------------------------------------------
// Sort phase 1: histogram of destinations (4 edges/thread for atomic MLP)
// ---------------------------------------------------------------------------
__global__ void hist_kernel(const int* __restrict__ refB, int E) {
    int base = (blockIdx.x * blockDim.x + threadIdx.x) * 4;
    if (base + 3 < E) {
        int4 d = *(const int4*)(refB + base);
        atomicAdd(&g_hist[d.x], 1);
        atomicAdd(&g_hist[d.y], 1);
        atomicAdd(&g_hist[d.z], 1);
        atomicAdd(&g_hist[d.w], 1);
    } else {
        for (int i = base; i < E; i++) atomicAdd(&g_hist[refB[i]], 1);
    }
}

// ---------------------------------------------------------------------------
// Sort phase 2 (fused): per-block exclusive scan; block total claims a region
// base via atomicAdd on g_hist[N+1]. Region order is arbitrary; accum only
// needs per-node (start, count).
// ---------------------------------------------------------------------------
__global__ __launch_bounds__(256)
void scan_fused_kernel(int N) {
    __shared__ int warp_pref[8];
    __shared__ int block_base;
    int t = threadIdx.x, lane = t & 31, wid = t >> 5;
    int node = blockIdx.x * 256 + t;
    int v = (node < N) ? g_hist[node] : 0;

    int x = v;
#pragma unroll
    for (int off = 1; off < 32; off <<= 1) {
        int y = __shfl_up_sync(0xFFFFFFFFu, x, off);
        if (lane >= off) x += y;
    }
    if (lane == 31) warp_pref[wid] = x;
    __syncthreads();
    if (wid == 0) {
        int ws = (lane < 8) ? warp_pref[lane] : 0;
        int wx = ws;
#pragma unroll
        for (int off = 1; off < 8; off <<= 1) {
            int y = __shfl_up_sync(0xFFFFFFFFu, wx, off);
            if (lane >= off) wx += y;
        }
        if (lane < 8) warp_pref[lane] = wx - ws;
        if (lane == 7) block_base = atomicAdd(&g_hist[N + 1], wx);
    }
    __syncthreads();
    if (node < N) {
        int start = block_base + warp_pref[wid] + x - v;
        g_start[node]  = start;
        g_cursor[node] = start;
    }
}

// ---------------------------------------------------------------------------
// Sort phase 3: bucket reorder (4 edges/thread for atomic MLP)
// ---------------------------------------------------------------------------
__global__ void reorder_kernel(const int* __restrict__ refA,
                               const int* __restrict__ refB, int E) {
    int base = (blockIdx.x * blockDim.x + threadIdx.x) * 4;
    if (base + 3 < E) {
        int4 d = *(const int4*)(refB + base);
        int4 a = *(const int4*)(refA + base);
        int p0 = atomicAdd(&g_cursor[d.x], 1);
        int p1 = atomicAdd(&g_cursor[d.y], 1);
        int p2 = atomicAdd(&g_cursor[d.z], 1);
        int p3 = atomicAdd(&g_cursor[d.w], 1);
        g_src[p0] = a.x;
        g_src[p1] = a.y;
        g_src[p2] = a.z;
        g_src[p3] = a.w;
    } else {
        for (int i = base; i < E; i++) {
            int pos = atomicAdd(&g_cursor[refB[i]], 1);
            g_src[pos] = refA[i];
        }
    }
}

// ---------------------------------------------------------------------------
// GEMM: Y = X @ W, smem-staged tf32 wmma.
// 256 threads / 8 warps; warp (wm, wn) owns a 32x32 tile: wm = warp&1 (rows),
// wn = warp>>1 (cols). W resident in padded smem for the whole block life;
// A tiles of 64 rows grid-strided. tf32 conversion applied during smem fill.
// ---------------------------------------------------------------------------
#define LDP 132   // padded leading dim (floats)
#define GEMM_SMEM_FLOATS (128 * LDP + 64 * LDP)
#define GEMM_SMEM_BYTES  (GEMM_SMEM_FLOATS * 4)

__global__ __launch_bounds__(256, 2)
void gemm_tf32_kernel(const float* __restrict__ X,
                      const float* __restrict__ W,
                      int n_mtiles) {   // tiles of 64 rows
    extern __shared__ float smem[];
    float* sW = smem;                 // 128 x LDP
    float* sA = smem + 128 * LDP;     // 64 x LDP

    int tid = threadIdx.x;
    int lane = tid & 31;
    int warp = tid >> 5;
    int wm = warp & 1;      // 0..1 -> 32-row half
    int wn = warp >> 1;     // 0..3 -> 32-col quarter

    // Load W (128x128) into padded smem, converting to tf32 once.
    const float4* W4 = (const float4*)W;
    for (int i = tid; i < 4096; i += 256) {
        float4 v = W4[i];
        v.x = wmma::__float_to_tf32(v.x);
        v.y = wmma::__float_to_tf32(v.y);
        v.z = wmma::__float_to_tf32(v.z);
        v.w = wmma::__float_to_tf32(v.w);
        int r = i >> 5;
        int c = (i & 31) << 2;
        *(float4*)(sW + r * LDP + c) = v;
    }
    __syncthreads();

    for (int mt = blockIdx.x; mt < n_mtiles; mt += gridDim.x) {
        size_t row0 = (size_t)mt * 64;

        // Stage A tile (64x128) coalesced, tf32-converted
        const float4* X4 = (const float4*)(X + row0 * 128);
        for (int i = tid; i < 2048; i += 256) {
            float4 v = X4[i];
            v.x = wmma::__float_to_tf32(v.x);
            v.y = wmma::__float_to_tf32(v.y);
            v.z = wmma::__float_to_tf32(v.z);
            v.w = wmma::__float_to_tf32(v.w);
            int r = i >> 5;
            int c = (i & 31) << 2;
            *(float4*)(sA + r * LDP + c) = v;
        }
        __syncthreads();

        wmma::fragment<wmma::accumulator, 16, 16, 8, float> acc[2][2];
#pragma unroll
        for (int mi = 0; mi < 2; mi++)
#pragma unroll
            for (int ni = 0; ni < 2; ni++)
                wmma::fill_fragment(acc[mi][ni], 0.0f);

#pragma unroll
        for (int kf = 0; kf < 16; kf++) {
            wmma::fragment<wmma::matrix_a, 16, 16, 8, wmma::precision::tf32,
                           wmma::row_major> a0, a1;
            wmma::load_matrix_sync(a0, sA + (wm * 32 + 0)  * LDP + kf * 8, LDP);
            wmma::load_matrix_sync(a1, sA + (wm * 32 + 16) * LDP + kf * 8, LDP);
            wmma::fragment<wmma::matrix_b, 16, 16, 8, wmma::precision::tf32,
                           wmma::row_major> b0, b1;
            wmma::load_matrix_sync(b0, sW + kf * 8 * LDP + wn * 32, LDP);
            wmma::load_matrix_sync(b1, sW + kf * 8 * LDP + wn * 32 + 16, LDP);
            wmma::mma_sync(acc[0][0], a0, b0, acc[0][0]);
            wmma::mma_sync(acc[0][1], a0, b1, acc[0][1]);
            wmma::mma_sync(acc[1][0], a1, b0, acc[1][0]);
            wmma::mma_sync(acc[1][1], a1, b1, acc[1][1]);
        }
        __syncthreads();   // all warps done reading sA -> reuse as epi staging

        // Epilogue: per-warp fp32 staging (in sA region), convert, STG.128 fp16
        float* epi = sA + warp * 384;   // 16x20 floats per warp, disjoint
#pragma unroll
        for (int mi = 0; mi < 2; mi++) {
#pragma unroll
            for (int ni = 0; ni < 2; ni++) {
                wmma::store_matrix_sync(epi, acc[mi][ni], 20, wmma::mem_row_major);
                __syncwarp();
                int er = lane & 15;
                int eh = lane >> 4;
                const float* src = epi + er * 20 + eh * 8;
                float4 v0 = *(const float4*)(src);
                float4 v1 = *(const float4*)(src + 4);
                __half2 h[4];
                h[0] = __floats2half2_rn(v0.x, v0.y);
                h[1] = __floats2half2_rn(v0.z, v0.w);
                h[2] = __floats2half2_rn(v1.x, v1.y);
                h[3] = __floats2half2_rn(v1.z, v1.w);
                size_t grow = row0 + wm * 32 + mi * 16 + er;
                int gcol = wn * 32 + ni * 16 + eh * 8;
                *(uint4*)(g_Yh + grow * 128 + gcol) = *(uint4*)h;
                __syncwarp();
            }
        }
        __syncthreads();   // before next iteration overwrites sA
    }
}

// Scalar tail for rows not covered by 64-row tiles (32 rows at N=100000)
__global__ void gemm_tail_kernel(const float* __restrict__ X,
                                 const float* __restrict__ W,
                                 int row_start, int n_rows) {
    int r = row_start + blockIdx.x;
    if ((int)blockIdx.x >= n_rows) return;
    int j = threadIdx.x;
    float acc = 0.0f;
#pragma unroll 8
    for (int k = 0; k < 128; k++)
        acc += X[(size_t)r * 128 + k] * W[(size_t)k * 128 + j];
    g_Yh[(size_t)r * 128 + j] = __float2half_rn(acc);
}

// ---------------------------------------------------------------------------
// Accumulate: one warp per destination node. fp16 gather, fp32 register
// accumulation, bias folded in, single fp32 write. end = start + count.
// ---------------------------------------------------------------------------
__global__ __launch_bounds__(256)
void accum_kernel(const float* __restrict__ b, float* __restrict__ out, int N) {
    int node = (blockIdx.x * blockDim.x + threadIdx.x) >> 5;
    int lane = threadIdx.x & 31;
    if (node >= N) return;
    int s = __ldg(&g_start[node]);
    int e = s + __ldg(&g_hist[node]);

    const uint2* Y2 = (const uint2*)g_Yh;
    float4 acc = make_float4(0.f, 0.f, 0.f, 0.f);
    int i = s;
    for (; i + 4 <= e; i += 4) {
        int s0 = g_src[i], s1 = g_src[i + 1], s2 = g_src[i + 2], s3 = g_src[i + 3];
        uint2 r0 = Y2[(size_t)s0 * 32 + lane];
        uint2 r1 = Y2[(size_t)s1 * 32 + lane];
        uint2 r2 = Y2[(size_t)s2 * 32 + lane];
        uint2 r3 = Y2[(size_t)s3 * 32 + lane];
        float2 a0 = __half22float2(*(__half2*)&r0.x), a1 = __half22float2(*(__half2*)&r0.y);
        float2 b0 = __half22float2(*(__half2*)&r1.x), b1 = __half22float2(*(__half2*)&r1.y);
        float2 c0 = __half22float2(*(__half2*)&r2.x), c1 = __half22float2(*(__half2*)&r2.y);
        float2 d0 = __half22float2(*(__half2*)&r3.x), d1 = __half22float2(*(__half2*)&r3.y);
        acc.x += (a0.x + b0.x) + (c0.x + d0.x);
        acc.y += (a0.y + b0.y) + (c0.y + d0.y);
        acc.z += (a1.x + b1.x) + (c1.x + d1.x);
        acc.w += (a1.y + b1.y) + (c1.y + d1.y);
    }
    for (; i < e; i++) {
        uint2 r0 = Y2[(size_t)g_src[i] * 32 + lane];
        float2 a0 = __half22float2(*(__half2*)&r0.x), a1 = __half22float2(*(__half2*)&r0.y);
        acc.x += a0.x; acc.y += a0.y; acc.z += a1.x; acc.w += a1.y;
    }

    float4 bv = ((const float4*)b)[lane];
    acc.x += bv.x; acc.y += bv.y; acc.z += bv.z; acc.w += bv.w;
    ((float4*)(out + (size_t)node * 128))[lane] = acc;
}

// ---------------------------------------------------------------------------
// Launch: two parallel branches (GEMM || sort chain), join, accum.
// ---------------------------------------------------------------------------
extern "C" void kernel_launch(void* const* d_in, const int* in_sizes, int n_in,
                              void* d_out, int out_size) {
    const float* X    = (const float*)d_in[0];
    const int*   refA = (const int*)d_in[1];
    const int*   refB = (const int*)d_in[2];
    const float* W    = (const float*)d_in[3];
    const float* b    = (const float*)d_in[4];
    float* out = (float*)d_out;

    int N = in_sizes[0] / 128;   // 100000
    int E = in_sizes[1];         // 640000
    int NB = (N + 255) / 256;

    // Fork side stream off the capture (legacy) stream
    cudaEventRecord(g_ss.fork, 0);
    cudaStreamWaitEvent(g_ss.s, g_ss.fork, 0);

    // --- Branch B (side stream): counting sort of edges by destination ---
    void* hist_ptr = nullptr;
    cudaGetSymbolAddress(&hist_ptr, g_hist);
    cudaMemsetAsync(hist_ptr, 0, (size_t)(N + 2) * sizeof(int), g_ss.s);
    int ethreads = (E + 3) / 4;
    hist_kernel<<<(ethreads + 255) / 256, 256, 0, g_ss.s>>>(refB, E);
    scan_fused_kernel<<<NB, 256, 0, g_ss.s>>>(N);
    reorder_kernel<<<(ethreads + 255) / 256, 256, 0, g_ss.s>>>(refA, refB, E);
    cudaEventRecord(g_ss.join, g_ss.s);

    // --- Branch A (capture stream): Y = X @ W ---
    static bool attr_set = false;
    if (!attr_set) {
        cudaFuncSetAttribute(gemm_tf32_kernel,
                             cudaFuncAttributeMaxDynamicSharedMemorySize,
                             GEMM_SMEM_BYTES);
        attr_set = true;
    }
    int n_mtiles = N / 64;
    gemm_tf32_kernel<<<296, 256, GEMM_SMEM_BYTES>>>(X, W, n_mtiles);
    int tail = N - n_mtiles * 64;
    if (tail > 0)
        gemm_tail_kernel<<<tail, 128>>>(X, W, n_mtiles * 64, tail);

    // --- Join, then per-node register accumulation + bias ---
    cudaStreamWaitEvent(0, g_ss.join, 0);
    accum_kernel<<<(N * 32 + 255) / 256, 256>>>(b, out, N);
}

// round 7
// speedup vs baseline: 1.4258x; 1.4258x over previous
#include <cuda_runtime.h>
#include <cuda_fp16.h>
#include <cuda_bf16.h>
#include <mma.h>

using namespace nvcuda;

#define MAX_NODES 100000
#define MAX_EDGES 640000

// Scratch (device globals — allocation in kernel_launch is forbidden)
__device__ float g_Y[(size_t)MAX_NODES * 128];          // Y = X@W fp32 (51.2 MB)
__device__ int   g_hist[MAX_NODES + 256];               // counts; [N+1] = base counter
__device__ int   g_start[MAX_NODES + 1];
__device__ int   g_cursor[MAX_NODES];
__device__ int   g_src[MAX_EDGES];                      // sources grouped by dest

// Static-initializer stream/event creation (host-side).
struct SideStream {
    cudaStream_t s;
    cudaEvent_t fork, join;
    SideStream() {
        cudaStreamCreateWithFlags(&s, cudaStreamNonBlocking);
        cudaEventCreateWithFlags(&fork, cudaEventDisableTiming);
        cudaEventCreateWithFlags(&join, cudaEventDisableTiming);
    }
};
static SideStream g_ss;

// ---------------------------------------------------------------------------
// Sort phase 1: histogram of destinations (4 edges/thread for atomic MLP)
// ---------------------------------------------------------------------------
__global__ void hist_kernel(const int* __restrict__ refB, int E) {
    int base = (blockIdx.x * blockDim.x + threadIdx.x) * 4;
    if (base + 3 < E) {
        int4 d = *(const int4*)(refB + base);
        atomicAdd(&g_hist[d.x], 1);
        atomicAdd(&g_hist[d.y], 1);
        atomicAdd(&g_hist[d.z], 1);
        atomicAdd(&g_hist[d.w], 1);
    } else {
        for (int i = base; i < E; i++) atomicAdd(&g_hist[refB[i]], 1);
    }
}

// ---------------------------------------------------------------------------
// Sort phase 2 (fused): per-block exclusive scan; block total claims a region
// base via atomicAdd on g_hist[N+1]. Region order arbitrary; accum only needs
// per-node (start, count).
// ---------------------------------------------------------------------------
__global__ __launch_bounds__(256)
void scan_fused_kernel(int N) {
    __shared__ int warp_pref[8];
    __shared__ int block_base;
    int t = threadIdx.x, lane = t & 31, wid = t >> 5;
    int node = blockIdx.x * 256 + t;
    int v = (node < N) ? g_hist[node] : 0;

    int x = v;
#pragma unroll
    for (int off = 1; off < 32; off <<= 1) {
        int y = __shfl_up_sync(0xFFFFFFFFu, x, off);
        if (lane >= off) x += y;
    }
    if (lane == 31) warp_pref[wid] = x;
    __syncthreads();
    if (wid == 0) {
        int ws = (lane < 8) ? warp_pref[lane] : 0;
        int wx = ws;
#pragma unroll
        for (int off = 1; off < 8; off <<= 1) {
            int y = __shfl_up_sync(0xFFFFFFFFu, wx, off);
            if (lane >= off) wx += y;
        }
        if (lane < 8) warp_pref[lane] = wx - ws;
        if (lane == 7) block_base = atomicAdd(&g_hist[N + 1], wx);
    }
    __syncthreads();
    if (node < N) {
        int start = block_base + warp_pref[wid] + x - v;
        g_start[node]  = start;
        g_cursor[node] = start;
    }
}

// ---------------------------------------------------------------------------
// Sort phase 3: bucket reorder (4 edges/thread for atomic MLP)
// ---------------------------------------------------------------------------
__global__ void reorder_kernel(const int* __restrict__ refA,
                               const int* __restrict__ refB, int E) {
    int base = (blockIdx.x * blockDim.x + threadIdx.x) * 4;
    if (base + 3 < E) {
        int4 d = *(const int4*)(refB + base);
        int4 a = *(const int4*)(refA + base);
        int p0 = atomicAdd(&g_cursor[d.x], 1);
        int p1 = atomicAdd(&g_cursor[d.y], 1);
        int p2 = atomicAdd(&g_cursor[d.z], 1);
        int p3 = atomicAdd(&g_cursor[d.w], 1);
        g_src[p0] = a.x;
        g_src[p1] = a.y;
        g_src[p2] = a.z;
        g_src[p3] = a.w;
    } else {
        for (int i = base; i < E; i++) {
            int pos = atomicAdd(&g_cursor[refB[i]], 1);
            g_src[pos] = refA[i];
        }
    }
}

// ---------------------------------------------------------------------------
// GEMM: Y = X @ W, fp16 wmma (m16n16k16, LDSM-backed loads), fp32 accum,
// direct fp32 global store. 256 threads / 8 warps; warp (wm, wn) owns 32x32.
// W resident in fp16 smem; A tiles (64x128) double-buffered with register
// prefetch -> ONE syncthreads per tile.
// ---------------------------------------------------------------------------
#define LDH 136   // padded leading dim (halves); 272 B rows spread banks
#define SW_HALFS   (128 * LDH)
#define SA_HALFS   (64 * LDH)
#define GEMM_SMEM_BYTES ((SW_HALFS + 2 * SA_HALFS) * 2)

__global__ __launch_bounds__(256, 2)
void gemm_f16_kernel(const float* __restrict__ X,
                     const float* __restrict__ W,
                     int n_mtiles) {   // tiles of 64 rows
    extern __shared__ __half smem[];
    __half* sW  = smem;                       // 128 x LDH
    __half* sA0 = smem + SW_HALFS;            // 64 x LDH
    __half* sA1 = sA0 + SA_HALFS;             // 64 x LDH

    int tid = threadIdx.x;
    int warp = tid >> 5;
    int wm = warp & 1;      // 32-row half of the 64-row tile
    int wn = warp >> 1;     // 32-col quarter

    // Load W (128x128 fp32) -> fp16 smem (once per block)
    const float4* W4 = (const float4*)W;
    for (int i = tid; i < 4096; i += 256) {
        float4 v = W4[i];
        int r = i >> 5;
        int c = (i & 31) << 2;
        __half2 h0 = __floats2half2_rn(v.x, v.y);
        __half2 h1 = __floats2half2_rn(v.z, v.w);
        *(__half2*)(sW + r * LDH + c)     = h0;
        *(__half2*)(sW + r * LDH + c + 2) = h1;
    }

    // Prefetch first A tile into registers
    float4 pf[8];
    int mt = blockIdx.x;
    if (mt < n_mtiles) {
        const float4* X4 = (const float4*)(X + (size_t)mt * 64 * 128);
#pragma unroll
        for (int j = 0; j < 8; j++) pf[j] = X4[tid + j * 256];
        // stage into sA0
#pragma unroll
        for (int j = 0; j < 8; j++) {
            int i = tid + j * 256;
            int r = i >> 5;
            int c = (i & 31) << 2;
            __half2 h0 = __floats2half2_rn(pf[j].x, pf[j].y);
            __half2 h1 = __floats2half2_rn(pf[j].z, pf[j].w);
            *(__half2*)(sA0 + r * LDH + c)     = h0;
            *(__half2*)(sA0 + r * LDH + c + 2) = h1;
        }
    }
    __syncthreads();   // W + first A tile visible

    int buf = 0;
    for (; mt < n_mtiles; mt += gridDim.x) {
        int nxt = mt + gridDim.x;
        // Issue prefetch LDGs for the next tile (latency hidden under compute)
        if (nxt < n_mtiles) {
            const float4* X4 = (const float4*)(X + (size_t)nxt * 64 * 128);
#pragma unroll
            for (int j = 0; j < 8; j++) pf[j] = X4[tid + j * 256];
        }

        const __half* sA = buf ? sA1 : sA0;
        wmma::fragment<wmma::accumulator, 16, 16, 16, float> acc[2][2];
#pragma unroll
        for (int mi = 0; mi < 2; mi++)
#pragma unroll
            for (int ni = 0; ni < 2; ni++)
                wmma::fill_fragment(acc[mi][ni], 0.0f);

#pragma unroll
        for (int kf = 0; kf < 8; kf++) {
            wmma::fragment<wmma::matrix_a, 16, 16, 16, __half, wmma::row_major> a0, a1;
            wmma::load_matrix_sync(a0, sA + (wm * 32 + 0)  * LDH + kf * 16, LDH);
            wmma::load_matrix_sync(a1, sA + (wm * 32 + 16) * LDH + kf * 16, LDH);
            wmma::fragment<wmma::matrix_b, 16, 16, 16, __half, wmma::row_major> b0, b1;
            wmma::load_matrix_sync(b0, sW + kf * 16 * LDH + wn * 32, LDH);
            wmma::load_matrix_sync(b1, sW + kf * 16 * LDH + wn * 32 + 16, LDH);
            wmma::mma_sync(acc[0][0], a0, b0, acc[0][0]);
            wmma::mma_sync(acc[0][1], a0, b1, acc[0][1]);
            wmma::mma_sync(acc[1][0], a1, b0, acc[1][0]);
            wmma::mma_sync(acc[1][1], a1, b1, acc[1][1]);
        }

        // Epilogue: direct fp32 store to global
        size_t row0 = (size_t)mt * 64 + wm * 32;
#pragma unroll
        for (int mi = 0; mi < 2; mi++)
#pragma unroll
            for (int ni = 0; ni < 2; ni++)
                wmma::store_matrix_sync(
                    g_Y + (row0 + mi * 16) * 128 + wn * 32 + ni * 16,
                    acc[mi][ni], 128, wmma::mem_row_major);

        // Stage prefetched tile into the other buffer, single sync
        if (nxt < n_mtiles) {
            __half* dst = buf ? sA0 : sA1;
#pragma unroll
            for (int j = 0; j < 8; j++) {
                int i = tid + j * 256;
                int r = i >> 5;
                int c = (i & 31) << 2;
                __half2 h0 = __floats2half2_rn(pf[j].x, pf[j].y);
                __half2 h1 = __floats2half2_rn(pf[j].z, pf[j].w);
                *(__half2*)(dst + r * LDH + c)     = h0;
                *(__half2*)(dst + r * LDH + c + 2) = h1;
            }
            __syncthreads();
        }
        buf ^= 1;
    }
}

// Scalar tail for rows not covered by 64-row tiles (32 rows at N=100000)
__global__ void gemm_tail_kernel(const float* __restrict__ X,
                                 const float* __restrict__ W,
                                 int row_start, int n_rows) {
    int r = row_start + blockIdx.x;
    if ((int)blockIdx.x >= n_rows) return;
    int j = threadIdx.x;
    float acc = 0.0f;
#pragma unroll 8
    for (int k = 0; k < 128; k++)
        acc += X[(size_t)r * 128 + k] * W[(size_t)k * 128 + j];
    g_Y[(size_t)r * 128 + j] = acc;
}

// ---------------------------------------------------------------------------
// Accumulate: one warp per destination node. fp32 gather (LDG.128/lane/edge),
// register accumulation, bias folded in. end = start + count.
// ---------------------------------------------------------------------------
__global__ __launch_bounds__(256)
void accum_kernel(const float* __restrict__ b, float* __restrict__ out, int N) {
    int node = (blockIdx.x * blockDim.x + threadIdx.x) >> 5;
    int lane = threadIdx.x & 31;
    if (node >= N) return;
    int s = __ldg(&g_start[node]);
    int e = s + __ldg(&g_hist[node]);

    const float4* Y4 = (const float4*)g_Y;
    float4 acc = make_float4(0.f, 0.f, 0.f, 0.f);
    int i = s;
    for (; i + 4 <= e; i += 4) {
        int s0 = g_src[i], s1 = g_src[i + 1], s2 = g_src[i + 2], s3 = g_src[i + 3];
        float4 v0 = Y4[(size_t)s0 * 32 + lane];
        float4 v1 = Y4[(size_t)s1 * 32 + lane];
        float4 v2 = Y4[(size_t)s2 * 32 + lane];
        float4 v3 = Y4[(size_t)s3 * 32 + lane];
        acc.x += (v0.x + v1.x) + (v2.x + v3.x);
        acc.y += (v0.y + v1.y) + (v2.y + v3.y);
        acc.z += (v0.z + v1.z) + (v2.z + v3.z);
        acc.w += (v0.w + v1.w) + (v2.w + v3.w);
    }
    for (; i < e; i++) {
        float4 v0 = Y4[(size_t)g_src[i] * 32 + lane];
        acc.x += v0.x; acc.y += v0.y; acc.z += v0.z; acc.w += v0.w;
    }

    float4 bv = ((const float4*)b)[lane];
    acc.x += bv.x; acc.y += bv.y; acc.z += bv.z; acc.w += bv.w;
    ((float4*)(out + (size_t)node * 128))[lane] = acc;
}

// ---------------------------------------------------------------------------
// Launch: two parallel branches (GEMM || sort chain), join, accum.
// ---------------------------------------------------------------------------
extern "C" void kernel_launch(void* const* d_in, const int* in_sizes, int n_in,
                              void* d_out, int out_size) {
    const float* X    = (const float*)d_in[0];
    const int*   refA = (const int*)d_in[1];
    const int*   refB = (const int*)d_in[2];
    const float* W    = (const float*)d_in[3];
    const float* b    = (const float*)d_in[4];
    float* out = (float*)d_out;

    int N = in_sizes[0] / 128;   // 100000
    int E = in_sizes[1];         // 640000
    int NB = (N + 255) / 256;

    // Fork side stream off the capture (legacy) stream
    cudaEventRecord(g_ss.fork, 0);
    cudaStreamWaitEvent(g_ss.s, g_ss.fork, 0);

    // --- Branch B (side stream): counting sort of edges by destination ---
    void* hist_ptr = nullptr;
    cudaGetSymbolAddress(&hist_ptr, g_hist);
    cudaMemsetAsync(hist_ptr, 0, (size_t)(N + 2) * sizeof(int), g_ss.s);
    int ethreads = (E + 3) / 4;
    hist_kernel<<<(ethreads + 255) / 256, 256, 0, g_ss.s>>>(refB, E);
    scan_fused_kernel<<<NB, 256, 0, g_ss.s>>>(N);
    reorder_kernel<<<(ethreads + 255) / 256, 256, 0, g_ss.s>>>(refA, refB, E);
    cudaEventRecord(g_ss.join, g_ss.s);

    // --- Branch A (capture stream): Y = X @ W (fp16 wmma) ---
    cudaFuncSetAttribute(gemm_f16_kernel,
                         cudaFuncAttributeMaxDynamicSharedMemorySize,
                         GEMM_SMEM_BYTES);
    int n_mtiles = N / 64;
    gemm_f16_kernel<<<296, 256, GEMM_SMEM_BYTES>>>(X, W, n_mtiles);
    int tail = N - n_mtiles * 64;
    if (tail > 0)
        gemm_tail_kernel<<<tail, 128>>>(X, W, n_mtiles * 64, tail);

    // --- Join, then per-node register accumulation + bias ---
    cudaStreamWaitEvent(0, g_ss.join, 0);
    accum_kernel<<<(N * 32 + 255) / 256, 256>>>(b, out, N);
}

// round 8
// speedup vs baseline: 1.5714x; 1.1021x over previous
#include <cuda_runtime.h>
#include <cuda_fp16.h>
#include <cuda_bf16.h>
#include <mma.h>

using namespace nvcuda;

#define MAX_NODES 100000
#define MAX_EDGES 640000

// Scratch (device globals — allocation in kernel_launch is forbidden)
__device__ __half g_Yh[(size_t)MAX_NODES * 128];        // Y = X@W fp16 (25.6 MB)
__device__ int    g_hist[MAX_NODES + 256];              // counts; [N+1] = base counter
__device__ int    g_start[MAX_NODES + 1];
__device__ int    g_cursor[MAX_NODES];
__device__ int    g_src[MAX_EDGES];                     // sources grouped by dest

// Static-initializer stream/event creation (host-side).
struct SideStream {
    cudaStream_t s;
    cudaEvent_t fork, join;
    SideStream() {
        cudaStreamCreateWithFlags(&s, cudaStreamNonBlocking);
        cudaEventCreateWithFlags(&fork, cudaEventDisableTiming);
        cudaEventCreateWithFlags(&join, cudaEventDisableTiming);
    }
};
static SideStream g_ss;

// ---------------------------------------------------------------------------
// Sort phase 1: histogram of destinations (4 edges/thread for atomic MLP)
// ---------------------------------------------------------------------------
__global__ void hist_kernel(const int* __restrict__ refB, int E) {
    int base = (blockIdx.x * blockDim.x + threadIdx.x) * 4;
    if (base + 3 < E) {
        int4 d = *(const int4*)(refB + base);
        atomicAdd(&g_hist[d.x], 1);
        atomicAdd(&g_hist[d.y], 1);
        atomicAdd(&g_hist[d.z], 1);
        atomicAdd(&g_hist[d.w], 1);
    } else {
        for (int i = base; i < E; i++) atomicAdd(&g_hist[refB[i]], 1);
    }
}

// ---------------------------------------------------------------------------
// Sort phase 2 (fused): per-block exclusive scan; block total claims a region
// base via atomicAdd on g_hist[N+1]. Region order arbitrary; accum only needs
// per-node (start, count).
// ---------------------------------------------------------------------------
__global__ __launch_bounds__(256)
void scan_fused_kernel(int N) {
    __shared__ int warp_pref[8];
    __shared__ int block_base;
    int t = threadIdx.x, lane = t & 31, wid = t >> 5;
    int node = blockIdx.x * 256 + t;
    int v = (node < N) ? g_hist[node] : 0;

    int x = v;
#pragma unroll
    for (int off = 1; off < 32; off <<= 1) {
        int y = __shfl_up_sync(0xFFFFFFFFu, x, off);
        if (lane >= off) x += y;
    }
    if (lane == 31) warp_pref[wid] = x;
    __syncthreads();
    if (wid == 0) {
        int ws = (lane < 8) ? warp_pref[lane] : 0;
        int wx = ws;
#pragma unroll
        for (int off = 1; off < 8; off <<= 1) {
            int y = __shfl_up_sync(0xFFFFFFFFu, wx, off);
            if (lane >= off) wx += y;
        }
        if (lane < 8) warp_pref[lane] = wx - ws;
        if (lane == 7) block_base = atomicAdd(&g_hist[N + 1], wx);
    }
    __syncthreads();
    if (node < N) {
        int start = block_base + warp_pref[wid] + x - v;
        g_start[node]  = start;
        g_cursor[node] = start;
    }
}

// ---------------------------------------------------------------------------
// Sort phase 3: bucket reorder (4 edges/thread for atomic MLP)
// ---------------------------------------------------------------------------
__global__ void reorder_kernel(const int* __restrict__ refA,
                               const int* __restrict__ refB, int E) {
    int base = (blockIdx.x * blockDim.x + threadIdx.x) * 4;
    if (base + 3 < E) {
        int4 d = *(const int4*)(refB + base);
        int4 a = *(const int4*)(refA + base);
        int p0 = atomicAdd(&g_cursor[d.x], 1);
        int p1 = atomicAdd(&g_cursor[d.y], 1);
        int p2 = atomicAdd(&g_cursor[d.z], 1);
        int p3 = atomicAdd(&g_cursor[d.w], 1);
        g_src[p0] = a.x;
        g_src[p1] = a.y;
        g_src[p2] = a.z;
        g_src[p3] = a.w;
    } else {
        for (int i = base; i < E; i++) {
            int pos = atomicAdd(&g_cursor[refB[i]], 1);
            g_src[pos] = refA[i];
        }
    }
}

// ---------------------------------------------------------------------------
// GEMM: Y = X @ W, fp16 wmma (m16n16k16), fp32 accum, fp16 output via padded
// smem staging in the just-consumed sA buffer. 256 threads / 8 warps.
// A tiles (64x128) double-buffered with register prefetch.
// ---------------------------------------------------------------------------
#define LDH 136   // padded leading dim (halves)
#define SW_HALFS   (128 * LDH)
#define SA_HALFS   (64 * LDH)
#define GEMM_SMEM_BYTES ((SW_HALFS + 2 * SA_HALFS) * 2)

__global__ __launch_bounds__(256, 2)
void gemm_f16_kernel(const float* __restrict__ X,
                     const float* __restrict__ W,
                     int n_mtiles) {   // tiles of 64 rows
    extern __shared__ __half smem[];
    __half* sW  = smem;                       // 128 x LDH
    __half* sA0 = smem + SW_HALFS;            // 64 x LDH
    __half* sA1 = sA0 + SA_HALFS;             // 64 x LDH

    int tid = threadIdx.x;
    int lane = tid & 31;
    int warp = tid >> 5;
    int wm = warp & 1;      // 32-row half of the 64-row tile
    int wn = warp >> 1;     // 32-col quarter

    // Load W (128x128 fp32) -> fp16 smem (once per block)
    const float4* W4 = (const float4*)W;
    for (int i = tid; i < 4096; i += 256) {
        float4 v = W4[i];
        int r = i >> 5;
        int c = (i & 31) << 2;
        *(__half2*)(sW + r * LDH + c)     = __floats2half2_rn(v.x, v.y);
        *(__half2*)(sW + r * LDH + c + 2) = __floats2half2_rn(v.z, v.w);
    }

    // Prefetch first A tile into registers, stage into sA0
    float4 pf[8];
    int mt = blockIdx.x;
    if (mt < n_mtiles) {
        const float4* X4 = (const float4*)(X + (size_t)mt * 64 * 128);
#pragma unroll
        for (int j = 0; j < 8; j++) pf[j] = X4[tid + j * 256];
#pragma unroll
        for (int j = 0; j < 8; j++) {
            int i = tid + j * 256;
            int r = i >> 5;
            int c = (i & 31) << 2;
            *(__half2*)(sA0 + r * LDH + c)     = __floats2half2_rn(pf[j].x, pf[j].y);
            *(__half2*)(sA0 + r * LDH + c + 2) = __floats2half2_rn(pf[j].z, pf[j].w);
        }
    }
    __syncthreads();

    int buf = 0;
    for (; mt < n_mtiles; mt += gridDim.x) {
        int nxt = mt + gridDim.x;
        if (nxt < n_mtiles) {
            const float4* X4 = (const float4*)(X + (size_t)nxt * 64 * 128);
#pragma unroll
            for (int j = 0; j < 8; j++) pf[j] = X4[tid + j * 256];
        }

        __half* sAc = buf ? sA1 : sA0;
        wmma::fragment<wmma::accumulator, 16, 16, 16, float> acc[2][2];
#pragma unroll
        for (int mi = 0; mi < 2; mi++)
#pragma unroll
            for (int ni = 0; ni < 2; ni++)
                wmma::fill_fragment(acc[mi][ni], 0.0f);

#pragma unroll
        for (int kf = 0; kf < 8; kf++) {
            wmma::fragment<wmma::matrix_a, 16, 16, 16, __half, wmma::row_major> a0, a1;
            wmma::load_matrix_sync(a0, sAc + (wm * 32 + 0)  * LDH + kf * 16, LDH);
            wmma::load_matrix_sync(a1, sAc + (wm * 32 + 16) * LDH + kf * 16, LDH);
            wmma::fragment<wmma::matrix_b, 16, 16, 16, __half, wmma::row_major> b0, b1;
            wmma::load_matrix_sync(b0, sW + kf * 16 * LDH + wn * 32, LDH);
            wmma::load_matrix_sync(b1, sW + kf * 16 * LDH + wn * 32 + 16, LDH);
            wmma::mma_sync(acc[0][0], a0, b0, acc[0][0]);
            wmma::mma_sync(acc[0][1], a0, b1, acc[0][1]);
            wmma::mma_sync(acc[1][0], a1, b0, acc[1][0]);
            wmma::mma_sync(acc[1][1], a1, b1, acc[1][1]);
        }
        __syncthreads();   // all warps done reading sA[buf]; reuse as scratch

        // Epilogue: fp32 staging (ldm=20, per-warp disjoint), fp16 STG.128
        float* epi = (float*)sAc + warp * 320;
        size_t row0 = (size_t)mt * 64 + wm * 32;
#pragma unroll
        for (int mi = 0; mi < 2; mi++) {
#pragma unroll
            for (int ni = 0; ni < 2; ni++) {
                wmma::store_matrix_sync(epi, acc[mi][ni], 20, wmma::mem_row_major);
                __syncwarp();
                int er = lane & 15;
                int eh = lane >> 4;
                const float* src = epi + er * 20 + eh * 8;
                float4 v0 = *(const float4*)(src);
                float4 v1 = *(const float4*)(src + 4);
                __half2 h[4];
                h[0] = __floats2half2_rn(v0.x, v0.y);
                h[1] = __floats2half2_rn(v0.z, v0.w);
                h[2] = __floats2half2_rn(v1.x, v1.y);
                h[3] = __floats2half2_rn(v1.z, v1.w);
                *(uint4*)(g_Yh + (row0 + mi * 16 + er) * 128 +
                          wn * 32 + ni * 16 + eh * 8) = *(uint4*)h;
                __syncwarp();
            }
        }

        // Stage prefetched tile into the other buffer
        if (nxt < n_mtiles) {
            __half* dst = buf ? sA0 : sA1;
#pragma unroll
            for (int j = 0; j < 8; j++) {
                int i = tid + j * 256;
                int r = i >> 5;
                int c = (i & 31) << 2;
                *(__half2*)(dst + r * LDH + c)     = __floats2half2_rn(pf[j].x, pf[j].y);
                *(__half2*)(dst + r * LDH + c + 2) = __floats2half2_rn(pf[j].z, pf[j].w);
            }
        }
        __syncthreads();
        buf ^= 1;
    }
}

// Scalar tail for rows not covered by 64-row tiles (32 rows at N=100000)
__global__ void gemm_tail_kernel(const float* __restrict__ X,
                                 const float* __restrict__ W,
                                 int row_start, int n_rows) {
    int r = row_start + blockIdx.x;
    if ((int)blockIdx.x >= n_rows) return;
    int j = threadIdx.x;
    float acc = 0.0f;
#pragma unroll 8
    for (int k = 0; k < 128; k++)
        acc += X[(size_t)r * 128 + k] * W[(size_t)k * 128 + j];
    g_Yh[(size_t)r * 128 + j] = __float2half_rn(acc);
}

// ---------------------------------------------------------------------------
// Accumulate: one warp per destination node. fp16 gather (LDG.64/lane/edge),
// fp32 register accumulation, 8-deep index/gather MLP, bias folded in.
// ---------------------------------------------------------------------------
__global__ __launch_bounds__(256)
void accum_kernel(const float* __restrict__ b, float* __restrict__ out, int N) {
    int node = (blockIdx.x * blockDim.x + threadIdx.x) >> 5;
    int lane = threadIdx.x & 31;
    if (node >= N) return;
    int s = __ldg(&g_start[node]);
    int e = s + __ldg(&g_hist[node]);

    const uint2* Y2 = (const uint2*)g_Yh;
    float4 acc = make_float4(0.f, 0.f, 0.f, 0.f);
    int i = s;
    for (; i + 8 <= e; i += 8) {
        int idx[8];
#pragma unroll
        for (int j = 0; j < 8; j++) idx[j] = g_src[i + j];
        uint2 r[8];
#pragma unroll
        for (int j = 0; j < 8; j++) r[j] = Y2[(size_t)idx[j] * 32 + lane];
#pragma unroll
        for (int j = 0; j < 8; j++) {
            float2 lo = __half22float2(*(__half2*)&r[j].x);
            float2 hi = __half22float2(*(__half2*)&r[j].y);
            acc.x += lo.x; acc.y += lo.y; acc.z += hi.x; acc.w += hi.y;
        }
    }
    for (; i + 4 <= e; i += 4) {
        int idx[4];
#pragma unroll
        for (int j = 0; j < 4; j++) idx[j] = g_src[i + j];
        uint2 r[4];
#pragma unroll
        for (int j = 0; j < 4; j++) r[j] = Y2[(size_t)idx[j] * 32 + lane];
#pragma unroll
        for (int j = 0; j < 4; j++) {
            float2 lo = __half22float2(*(__half2*)&r[j].x);
            float2 hi = __half22float2(*(__half2*)&r[j].y);
            acc.x += lo.x; acc.y += lo.y; acc.z += hi.x; acc.w += hi.y;
        }
    }
    for (; i < e; i++) {
        uint2 r0 = Y2[(size_t)g_src[i] * 32 + lane];
        float2 lo = __half22float2(*(__half2*)&r0.x);
        float2 hi = __half22float2(*(__half2*)&r0.y);
        acc.x += lo.x; acc.y += lo.y; acc.z += hi.x; acc.w += hi.y;
    }

    float4 bv = ((const float4*)b)[lane];
    acc.x += bv.x; acc.y += bv.y; acc.z += bv.z; acc.w += bv.w;
    ((float4*)(out + (size_t)node * 128))[lane] = acc;
}

// ---------------------------------------------------------------------------
// Launch: two parallel branches (GEMM || sort + tail), join, accum.
// ---------------------------------------------------------------------------
extern "C" void kernel_launch(void* const* d_in, const int* in_sizes, int n_in,
                              void* d_out, int out_size) {
    const float* X    = (const float*)d_in[0];
    const int*   refA = (const int*)d_in[1];
    const int*   refB = (const int*)d_in[2];
    const float* W    = (const float*)d_in[3];
    const float* b    = (const float*)d_in[4];
    float* out = (float*)d_out;

    int N = in_sizes[0] / 128;   // 100000
    int E = in_sizes[1];         // 640000
    int NB = (N + 255) / 256;
    int n_mtiles = N / 64;
    int tail = N - n_mtiles * 64;

    // Fork side stream off the capture (legacy) stream
    cudaEventRecord(g_ss.fork, 0);
    cudaStreamWaitEvent(g_ss.s, g_ss.fork, 0);

    // --- Branch B (side stream): GEMM tail + counting sort ---
    if (tail > 0)
        gemm_tail_kernel<<<tail, 128, 0, g_ss.s>>>(X, W, n_mtiles * 64, tail);
    void* hist_ptr = nullptr;
    cudaGetSymbolAddress(&hist_ptr, g_hist);
    cudaMemsetAsync(hist_ptr, 0, (size_t)(N + 2) * sizeof(int), g_ss.s);
    int ethreads = (E + 3) / 4;
    hist_kernel<<<(ethreads + 255) / 256, 256, 0, g_ss.s>>>(refB, E);
    scan_fused_kernel<<<NB, 256, 0, g_ss.s>>>(N);
    reorder_kernel<<<(ethreads + 255) / 256, 256, 0, g_ss.s>>>(refA, refB, E);
    cudaEventRecord(g_ss.join, g_ss.s);

    // --- Branch A (capture stream): Y = X @ W (fp16 wmma) ---
    cudaFuncSetAttribute(gemm_f16_kernel,
                         cudaFuncAttributeMaxDynamicSharedMemorySize,
                         GEMM_SMEM_BYTES);
    gemm_f16_kernel<<<296, 256, GEMM_SMEM_BYTES>>>(X, W, n_mtiles);

    // --- Join, then per-node register accumulation + bias ---
    cudaStreamWaitEvent(0, g_ss.join, 0);
    accum_kernel<<<(N * 32 + 255) / 256, 256>>>(b, out, N);
}